// round 17
// baseline (speedup 1.0000x reference)
#include <cuda_runtime.h>
#include <cuda_bf16.h>
#include <math.h>
#include <cstdint>

// Problem constants (fixed shapes for this problem)
#define NMAX 100000
#define H 128
#define FIN 256

// -------- scratch (no allocation allowed) --------
__device__ float g_bufA[(size_t)NMAX * H];
__device__ float g_bufB[(size_t)NMAX * H];
__device__ float g_deg[NMAX];
__device__ float g_wbuf[16384 + 8 * 8192];           // bf16 weight fragments
__device__ float g_vfin[260];                        // fused final: v1[128] v2[128] c
__device__ __nv_bfloat16 g_hb16[(size_t)NMAX * H];   // bf16 hidden state
__device__ __nv_bfloat16 g_aggb16[(size_t)NMAX * H]; // bf16 aggregation / y0 buffer
__device__ int   g_is64;

__device__ __forceinline__ long long load_idx(const void* ei, long long i, int is64) {
    if (is64) return ((const long long*)ei)[i];
    return (long long)(((const int*)ei)[i]);
}

// ================ bf16 helpers ================
__device__ __forceinline__ uint32_t pack_bf16x2(float lo, float hi) {
    uint32_t r;
    asm("cvt.rn.bf16x2.f32 %0, %1, %2;" : "=r"(r) : "f"(hi), "f"(lo));
    return r;
}
__device__ __forceinline__ void mma_bf16(float* c, uint32_t a0, uint32_t a1,
                                         uint32_t a2, uint32_t a3,
                                         uint32_t b0, uint32_t b1) {
    asm volatile(
        "mma.sync.aligned.m16n8k16.row.col.f32.bf16.bf16.f32 "
        "{%0,%1,%2,%3}, {%4,%5,%6,%7}, {%8,%9}, {%0,%1,%2,%3};"
        : "+f"(c[0]), "+f"(c[1]), "+f"(c[2]), "+f"(c[3])
        : "r"(a0), "r"(a1), "r"(a2), "r"(a3), "r"(b0), "r"(b1));
}

// ================ merged prelude: ONE launch ================
// grid (32, 9), 256 threads.
//  y in [0,6]: prepW for weight y (m16n8k16 B-fragment order)
//  y == 7, x == 0: prep_final (fold final_W through nodepost_W / d_W3)
//  y == 7, x == 1: edge-index dtype detection (1024 odd-word samples)
//  y == 8: zero g_deg
__global__ void prelude_kernel(
    const float* W0, const float* W1, const float* W2, const float* W3,
    const float* W4, const float* W5, const float* W6,
    const float* npW, const float* npb, const float* d3W, const float* d3b,
    const float* fW, const float* fb,
    const unsigned int* ei, float* __restrict__ wbuf,
    float* __restrict__ vfin, float* __restrict__ deg, int n) {
    int t = threadIdx.x;
    int y = blockIdx.y;

    if (y < 7) {
        const float* W; float* dst; int K;
        switch (y) {
            case 0: W = W0; dst = wbuf;                K = 256; break;
            case 1: W = W1; dst = wbuf + 16384;        K = 128; break;
            case 2: W = W2; dst = wbuf + 16384 + 8192; K = 128; break;
            case 3: W = W3; dst = wbuf + 16384 + 2 * 8192; K = 128; break;
            case 4: W = W4; dst = wbuf + 16384 + 3 * 8192; K = 128; break;
            case 5: W = W5; dst = wbuf + 16384 + 4 * 8192; K = 128; break;
            default: W = W6; dst = wbuf + 16384 + 5 * 8192; K = 128; break;
        }
        int idx = blockIdx.x * 256 + t;
        int total = (K >> 4) * 16 * 32;
        if (idx >= total) return;
        int lane = idx & 31;
        int ntile = (idx >> 5) & 15;
        int kstep = idx >> 9;
        int k0 = kstep * 16 + (lane & 3) * 2;
        int nn = ntile * 8 + (lane >> 2);
        uint32_t b0 = pack_bf16x2(W[k0 * 128 + nn], W[(k0 + 1) * 128 + nn]);
        uint32_t b1 = pack_bf16x2(W[(k0 + 8) * 128 + nn], W[(k0 + 9) * 128 + nn]);
        ((uint2*)dst)[idx] = make_uint2(b0, b1);
    } else if (y == 7) {
        if (blockIdx.x == 0) {
            __shared__ float sw[256];
            __shared__ float red[128];
            if (t < 128) { sw[t] = fW[t]; sw[t + 128] = fW[t + 128]; }
            __syncthreads();
            if (t < 128) {
                float s1 = 0.f, s2 = 0.f;
#pragma unroll 8
                for (int j = 0; j < 128; j++) {
                    s1 += npW[t * 128 + j] * sw[j];
                    s2 += d3W[t * 128 + j] * sw[128 + j];
                }
                vfin[t] = s1;
                vfin[128 + t] = s2;
                red[t] = npb[t] * sw[t] + d3b[t] * sw[128 + t];
            }
            __syncthreads();
            for (int off = 64; off; off >>= 1) {
                if (t < off) red[t] += red[t + off];
                __syncthreads();
            }
            if (t == 0) vfin[256] = red[0] + fb[0];
        } else if (blockIdx.x == 1) {
            int any = 0;
#pragma unroll
            for (int j = 0; j < 4; j++)
                any |= (ei[2 * (t * 4 + j) + 1] != 0u);
            any = __syncthreads_or(any);
            if (t == 0) g_is64 = any ? 0 : 1;
        }
    } else {
        // zero deg: n floats over 32 blocks x 256 threads
        for (int i = blockIdx.x * 256 + t; i < n; i += 32 * 256) deg[i] = 0.f;
    }
}

__global__ void deg_kernel(const void* __restrict__ ei, long long E) {
    long long e = (long long)blockIdx.x * blockDim.x + threadIdx.x;
    if (e >= E) return;
    int is64 = g_is64;
    long long dst = load_idx(ei, E + e, is64);
    atomicAdd(&g_deg[dst], 1.0f);
}

// bf16 scatter-add: agg[dst] += h[src]; half-warp per edge (16 lanes x 16B).
__global__ void scatter_b16_kernel(const __nv_bfloat16* __restrict__ h,
                                   __nv_bfloat16* __restrict__ agg,
                                   const void* __restrict__ ei, long long E) {
    long long e = (long long)blockIdx.x * 16 + (threadIdx.x >> 4);
    int lane = threadIdx.x & 15;
    if (e >= E) return;
    int is64 = g_is64;
    long long src = load_idx(ei, e, is64);
    long long dst = load_idx(ei, E + e, is64);
    uint4 v = ((const uint4*)(h + src * H))[lane];
    __nv_bfloat16* p = agg + dst * H + lane * 8;
    asm volatile("red.global.add.noftz.v4.bf16x2 [%0], {%1, %2, %3, %4};"
                 :: "l"(p), "r"(v.x), "r"(v.y), "r"(v.z), "r"(v.w) : "memory");
}

// ================ fused final: out = sigmoid(h2.v1 + y2.v2 + c) ================
__global__ void final_fused_kernel(const float* __restrict__ h2, const float* __restrict__ y2,
                                   const float* __restrict__ v, float* __restrict__ out, int n) {
    long long wg = (long long)blockIdx.x * 8 + (threadIdx.x >> 5);
    int lane = threadIdx.x & 31;
    if (wg >= n) return;
    float4 f = *(const float4*)(h2 + wg * 128 + lane * 4);
    float4 w1 = *(const float4*)(v + lane * 4);
    float4 d = *(const float4*)(y2 + wg * 128 + lane * 4);
    float4 w2 = *(const float4*)(v + 128 + lane * 4);
    float s = f.x * w1.x + f.y * w1.y + f.z * w1.z + f.w * w1.w
            + d.x * w2.x + d.y * w2.y + d.z * w2.z + d.w * w2.w;
#pragma unroll
    for (int off = 16; off; off >>= 1) s += __shfl_xor_sync(0xFFFFFFFFu, s, off);
    if (lane == 0) {
        float z = s + v[256];
        out[wg] = 1.0f / (1.0f + expf(-z));
    }
}

// ================ persistent tensor-core GEMM (bf16 m16n8k16) ================
// C = act( A1@W1 + (1/max(deg,1) ⊙ A2)@W2 + bias )
// A1f fp32 OR A1b bf16 (one non-null if K1>0); A2 bf16 (scaled by 1/max(deg,1)).
// Outputs Cf fp32 / Cb16 bf16 (nullable; Cb16 may alias A1b — row ownership).
// zeroAgg: epilogue zeroes that buffer's rows [bm, bm+128).
// R14-proven launch_bounds (no minBlocks contract).
#define AROW 20
#define ABUF (128 * AROW)

__global__ void __launch_bounds__(256)
tc_gemm(const float* __restrict__ A1f, const __nv_bfloat16* __restrict__ A1b, int K1,
        const float* __restrict__ Wf1,
        const __nv_bfloat16* __restrict__ A2, int K2, const float* __restrict__ Wf2,
        const float* __restrict__ degraw, const float* __restrict__ bias,
        float* __restrict__ Cf, __nv_bfloat16* __restrict__ Cb16,
        __nv_bfloat16* __restrict__ zeroAgg,
        int M, int act) {
    extern __shared__ float smem[];
    int KT = K1 + K2;
    float* sW = smem;                         // KT*64 uint32 (fragment order)
    float* sA = smem + (size_t)KT * 64;       // ABUF uint32
    float* sB = sA + ABUF;                    // 128 floats bias

    int t = threadIdx.x, warp = t >> 5, lane = t & 31;
    int wm = (warp & 3) * 32;
    int wn = (warp >> 2) * 64;

    {
        const float4* s1 = (const float4*)Wf1;
        float4* d = (float4*)sW;
        for (int i = t; i < K1 * 16; i += 256) d[i] = s1[i];
        if (K2 > 0) {
            const float4* s2 = (const float4*)Wf2;
            float4* d2 = (float4*)(sW + (size_t)K1 * 64);
            for (int i = t; i < K2 * 16; i += 256) d2[i] = s2[i];
        }
        if (t < 128) sB[t] = bias[t];
    }
    __syncthreads();

    int nMB = (M + 127) >> 7;
    int nP = KT >> 5;

    int lrow = t >> 3;         // 0..31, rows lrow + j*32
    int lc4 = (t & 7) * 4;     // element offset 0..28

    for (int mb = blockIdx.x; mb < nMB; mb += gridDim.x) {
        int bm = mb << 7;

        float acc[2][8][4];
#pragma unroll
        for (int a = 0; a < 2; a++)
#pragma unroll
            for (int b = 0; b < 8; b++)
#pragma unroll
                for (int c = 0; c < 4; c++) acc[a][b][c] = 0.f;

        float4 rv[4];
#pragma unroll
        for (int j = 0; j < 4; j++) {
            int row = lrow + j * 32;
            int grow = bm + row;
            float4 v = make_float4(0.f, 0.f, 0.f, 0.f);
            if (grow < M) {
                if (K1 > 0) {
                    if (A1f) {
                        v = *(const float4*)(A1f + (size_t)grow * K1 + lc4);
                    } else {
                        uint2 u = *(const uint2*)(A1b + (size_t)grow * K1 + lc4);
                        float2 p0 = __bfloat1622float2(*(__nv_bfloat162*)&u.x);
                        float2 p1 = __bfloat1622float2(*(__nv_bfloat162*)&u.y);
                        v = make_float4(p0.x, p0.y, p1.x, p1.y);
                    }
                } else {
                    uint2 u = *(const uint2*)(A2 + (size_t)grow * K2 + lc4);
                    float2 p0 = __bfloat1622float2(*(__nv_bfloat162*)&u.x);
                    float2 p1 = __bfloat1622float2(*(__nv_bfloat162*)&u.y);
                    float s = 1.0f / fmaxf(degraw[grow], 1.0f);
                    v = make_float4(p0.x * s, p0.y * s, p1.x * s, p1.y * s);
                }
            }
            rv[j] = v;
        }

        for (int p = 0; p < nP; p++) {
            __syncthreads();
#pragma unroll
            for (int j = 0; j < 4; j++) {
                int row = lrow + j * 32;
                uint32_t* st = (uint32_t*)sA + row * AROW + (lc4 >> 1);
                st[0] = pack_bf16x2(rv[j].x, rv[j].y);
                st[1] = pack_bf16x2(rv[j].z, rv[j].w);
            }
            __syncthreads();

            if (p + 1 < nP) {
                int kt = (p + 1) << 5;
#pragma unroll
                for (int j = 0; j < 4; j++) {
                    int row = lrow + j * 32;
                    int grow = bm + row;
                    float4 v = make_float4(0.f, 0.f, 0.f, 0.f);
                    if (grow < M) {
                        if (kt < K1) {
                            if (A1f) {
                                v = *(const float4*)(A1f + (size_t)grow * K1 + kt + lc4);
                            } else {
                                uint2 u = *(const uint2*)(A1b + (size_t)grow * K1 + kt + lc4);
                                float2 p0 = __bfloat1622float2(*(__nv_bfloat162*)&u.x);
                                float2 p1 = __bfloat1622float2(*(__nv_bfloat162*)&u.y);
                                v = make_float4(p0.x, p0.y, p1.x, p1.y);
                            }
                        } else {
                            int kp = kt - K1;
                            uint2 u = *(const uint2*)(A2 + (size_t)grow * K2 + kp + lc4);
                            float2 p0 = __bfloat1622float2(*(__nv_bfloat162*)&u.x);
                            float2 p1 = __bfloat1622float2(*(__nv_bfloat162*)&u.y);
                            float s = 1.0f / fmaxf(degraw[grow], 1.0f);
                            v = make_float4(p0.x * s, p0.y * s, p1.x * s, p1.y * s);
                        }
                    }
                    rv[j] = v;
                }
            }

            const uint32_t* aB = (const uint32_t*)sA;
#pragma unroll
            for (int ks = 0; ks < 2; ks++) {
                int kst = p * 2 + ks;
                uint2 bf[8];
                const uint2* wf = ((const uint2*)sW) + ((size_t)kst * 16 + (wn >> 3)) * 32 + lane;
#pragma unroll
                for (int j = 0; j < 8; j++) bf[j] = wf[j * 32];

#pragma unroll
                for (int mt = 0; mt < 2; mt++) {
                    int r = wm + mt * 16 + (lane >> 2);
                    int c = ks * 8 + (lane & 3);
                    uint32_t a0 = aB[r * AROW + c];
                    uint32_t a1 = aB[(r + 8) * AROW + c];
                    uint32_t a2 = aB[r * AROW + c + 4];
                    uint32_t a3 = aB[(r + 8) * AROW + c + 4];
#pragma unroll
                    for (int nt = 0; nt < 8; nt++)
                        mma_bf16(acc[mt][nt], a0, a1, a2, a3, bf[nt].x, bf[nt].y);
                }
            }
        }

#pragma unroll
        for (int mt = 0; mt < 2; mt++) {
            int r0 = bm + wm + mt * 16 + (lane >> 2);
#pragma unroll
            for (int nt = 0; nt < 8; nt++) {
                int col = wn + nt * 8 + (lane & 3) * 2;
                float b0 = sB[col], b1 = sB[col + 1];
                float v0 = acc[mt][nt][0] + b0;
                float v1 = acc[mt][nt][1] + b1;
                float v2 = acc[mt][nt][2] + b0;
                float v3 = acc[mt][nt][3] + b1;
                if (act) {
                    v0 = fmaxf(v0, 0.f); v1 = fmaxf(v1, 0.f);
                    v2 = fmaxf(v2, 0.f); v3 = fmaxf(v3, 0.f);
                }
                if (r0 < M) {
                    if (Cf)   *(float2*)(Cf + (size_t)r0 * 128 + col) = make_float2(v0, v1);
                    if (Cb16) *(uint32_t*)(Cb16 + (size_t)r0 * 128 + col) = pack_bf16x2(v0, v1);
                }
                if (r0 + 8 < M) {
                    if (Cf)   *(float2*)(Cf + (size_t)(r0 + 8) * 128 + col) = make_float2(v2, v3);
                    if (Cb16) *(uint32_t*)(Cb16 + (size_t)(r0 + 8) * 128 + col) = pack_bf16x2(v2, v3);
                }
            }
        }

        if (zeroAgg) {
            for (int i = t; i < 128 * 16; i += 256) {
                int row = bm + (i >> 4);
                if (row < M)
                    ((uint4*)(zeroAgg + (size_t)row * 128))[i & 15] =
                        make_uint4(0u, 0u, 0u, 0u);
            }
        }
    }
}

// -------- dist layer0: y0 = relu(e[N,5]@W0[5,128]+b0) -> bf16 --------
__global__ void dist0_kernel(const float* __restrict__ e, const float* __restrict__ W0,
                             const float* __restrict__ b0,
                             __nv_bfloat16* __restrict__ out, int n) {
    __shared__ float sW[5 * 128];
    __shared__ float sb[128];
    int t = threadIdx.x;  // 128
    for (int i = t; i < 5 * 128; i += 128) sW[i] = W0[i];
    sb[t] = b0[t];
    __syncthreads();
    for (long long nd = blockIdx.x; nd < n; nd += gridDim.x) {
        const float* ev = e + nd * 5;
        float v = sb[t];
        v += ev[0] * sW[0 * 128 + t];
        v += ev[1] * sW[1 * 128 + t];
        v += ev[2] * sW[2 * 128 + t];
        v += ev[3] * sW[3 * 128 + t];
        v += ev[4] * sW[4 * 128 + t];
        out[nd * 128 + t] = __float2bfloat16(fmaxf(v, 0.f));
    }
}

extern "C" void kernel_launch(void* const* d_in, const int* in_sizes, int n_in,
                              void* d_out, int out_size) {
    const float* x          = (const float*)d_in[0];
    const void*  ei         = d_in[1];
    const float* eattr      = (const float*)d_in[2];
    const float* pre_W      = (const float*)d_in[3];
    const float* pre_b      = (const float*)d_in[4];
    const float* c1_Ws      = (const float*)d_in[5];
    const float* c1_Wn      = (const float*)d_in[6];
    const float* c1_b       = (const float*)d_in[7];
    const float* c2_Ws      = (const float*)d_in[8];
    const float* c2_Wn      = (const float*)d_in[9];
    const float* c2_b       = (const float*)d_in[10];
    const float* nodepost_W = (const float*)d_in[11];
    const float* nodepost_b = (const float*)d_in[12];
    const float* d_W0       = (const float*)d_in[13];
    const float* d_b0       = (const float*)d_in[14];
    const float* d_W1       = (const float*)d_in[15];
    const float* d_b1       = (const float*)d_in[16];
    const float* d_W2       = (const float*)d_in[17];
    const float* d_b2       = (const float*)d_in[18];
    const float* d_W3       = (const float*)d_in[19];
    const float* d_b3       = (const float*)d_in[20];
    const float* final_W    = (const float*)d_in[21];
    const float* final_b    = (const float*)d_in[22];
    float* out = (float*)d_out;

    int n = in_sizes[0] / FIN;
    long long E = (long long)in_sizes[1] / 2;

    float *bufA, *bufB, *deg, *wbuf, *vfin;
    __nv_bfloat16 *hb16, *aggb16;
    cudaGetSymbolAddress((void**)&bufA, g_bufA);
    cudaGetSymbolAddress((void**)&bufB, g_bufB);
    cudaGetSymbolAddress((void**)&deg, g_deg);
    cudaGetSymbolAddress((void**)&wbuf, g_wbuf);
    cudaGetSymbolAddress((void**)&vfin, g_vfin);
    cudaGetSymbolAddress((void**)&hb16, g_hb16);
    cudaGetSymbolAddress((void**)&aggb16, g_aggb16);

    // fragment buffer layout
    float* f_pre  = wbuf;                  // K=256
    float* f_c1s  = wbuf + 16384;
    float* f_c1n  = f_c1s + 8192;
    float* f_c2s  = f_c1n + 8192;
    float* f_c2n  = f_c2s + 8192;
    float* f_d1   = f_c2n + 8192;
    float* f_d2   = f_d1 + 8192;

    const int SMEM_K256 = (256 * 64 + ABUF + 128) * 4;  // ~76 KB
    const int SMEM_K128 = (128 * 64 + ABUF + 128) * 4;  // ~43 KB
    cudaFuncSetAttribute(tc_gemm, cudaFuncAttributeMaxDynamicSharedMemorySize, SMEM_K256);

    const int nSM = 148;   // B200 (sm_100a)
    int nMB = (n + 127) / 128;
    int gemm_grid = nSM < nMB ? nSM : nMB;               // K=256 (1 CTA/SM, R14-proven)
    int gemm_grid2 = (2 * nSM) < nMB ? (2 * nSM) : nMB;  // K=128 (2 CTAs/SM by smem fit)

    int scat_grid = (int)((E + 15) / 16);

    // ---- prelude: detect + 7x prepW + prep_final + deg-zero, one launch ----
    {
        dim3 g(32, 9);
        prelude_kernel<<<g, 256>>>(pre_W, c1_Ws, c1_Wn, c2_Ws, c2_Wn, d_W1, d_W2,
                                   nodepost_W, nodepost_b, d_W3, d_b3,
                                   final_W, final_b,
                                   (const unsigned int*)ei, wbuf, vfin, deg, n);
    }
    deg_kernel<<<(int)((E + 255) / 256), 256>>>(ei, E);

    // ---- dist path first (bf16 intermediates; identical numerics) ----
    // y0 -> aggb16 (bf16); y1 -> hb16 (bf16); y2 -> bufB (fp32)
    dist0_kernel<<<2048, 128>>>(eattr, d_W0, d_b0, aggb16, n);
    tc_gemm<<<gemm_grid2, 256, SMEM_K128>>>(nullptr, aggb16, H, f_d1, nullptr, 0, nullptr,
                                            nullptr, d_b1, nullptr, hb16, nullptr, n, 1);
    tc_gemm<<<gemm_grid2, 256, SMEM_K128>>>(nullptr, hb16, H, f_d2, nullptr, 0, nullptr,
                                            nullptr, d_b2, bufB, nullptr, nullptr, n, 1);
    // bufB = y2, kept alive to the end

    // ---- feat path ----
    // pre: h0 = x @ pre_W + pre_b -> hb16 (overwrites y1, done); zeroes aggb16 (y0 done)
    tc_gemm<<<gemm_grid, 256, SMEM_K256>>>(x, nullptr, FIN, f_pre, nullptr, 0, nullptr,
                                           nullptr, pre_b, nullptr, hb16, aggb16, n, 0);

    scatter_b16_kernel<<<scat_grid, 256>>>(hb16, aggb16, ei, E);

    // h1 = relu(h0@c1_Ws + (1/deg)*agg1@c1_Wn + b) -> hb16 in place; re-zero aggb16
    tc_gemm<<<gemm_grid, 256, SMEM_K256>>>(nullptr, hb16, H, f_c1s, aggb16, H, f_c1n,
                                           deg, c1_b, nullptr, hb16, aggb16, n, 1);

    scatter_b16_kernel<<<scat_grid, 256>>>(hb16, aggb16, ei, E);

    // h2 = relu(h1@c2_Ws + (1/deg)*agg2@c2_Wn + b) -> bufA (fp32 for final dot)
    tc_gemm<<<gemm_grid, 256, SMEM_K256>>>(nullptr, hb16, H, f_c2s, aggb16, H, f_c2n,
                                           deg, c2_b, bufA, nullptr, nullptr, n, 1);

    // fused final: out = sigmoid(h2.v1 + y2.v2 + c)
    final_fused_kernel<<<(n + 7) / 8, 256>>>(bufA, bufB, vfin, out, n);
}